// round 9
// baseline (speedup 1.0000x reference)
#include <cuda_runtime.h>

#define QF 64
#define PTS_PER_WARP 432   // multiple of 16; 4630 warps -> 579 blocks <= 592 (4/SM) = ONE wave

__global__ void perslay_zero_kernel(float4* __restrict__ out, int n4) {
    int i = blockIdx.x * blockDim.x + threadIdx.x;
    if (i < n4) out[i] = make_float4(0.f, 0.f, 0.f, 0.f);
}

__device__ __forceinline__ float ex2_approx(float x) {
    float r;
    asm("ex2.approx.f32 %0, %1;" : "=f"(r) : "f"(x));
    return r;
}

// phi(x,y) for one q via pure-FFMA quadratic chain:
//   t = ((A*x + B)*x + C) + (Ay*y + By)*y  == -(ax(x-px))^2-(ay(y-py))^2, log2 units
//   4 FFMA -> 1 MUFU -> 1 FADD(acc)
__device__ __forceinline__ float gq(float x, float y,
                                    float A, float B, float C,
                                    float Ay, float By)
{
    const float u = fmaf(x, A, B);
    const float v = fmaf(x, u, C);
    const float w = fmaf(y, Ay, By);
    const float t = fmaf(y, w, v);
    return ex2_approx(t);
}

__global__ __launch_bounds__(256, 4) void perslay_kernel(
    const float2* __restrict__ xy,
    const int*    __restrict__ seg,
    const float*  __restrict__ sp,
    const float*  __restrict__ isg,
    float*        __restrict__ out,
    int n)
{
    const int warp_id = blockIdx.x * (blockDim.x >> 5) + (threadIdx.x >> 5);
    const int lane    = threadIdx.x & 31;
    const int start   = warp_id * PTS_PER_WARP;
    if (start >= n) return;
    const int end = min(start + PTS_PER_WARP, n);

    const int q0 = 2 * lane;
    const int q1 = q0 + 1;

    // sqrt(log2 e) folded into sigma scale so a bare ex2 replaces exp.
    const float SL  = 1.2011224087864498f;
    const float px0 = sp[q0],      px1 = sp[q1];
    const float py0 = sp[QF + q0], py1 = sp[QF + q1];
    const float ax0 = isg[q0]      * SL, ax1 = isg[q1]      * SL;
    const float ay0 = isg[QF + q0] * SL, ay1 = isg[QF + q1] * SL;

    const float A0  = -ax0 * ax0,       A1  = -ax1 * ax1;
    const float Ay0 = -ay0 * ay0,       Ay1 = -ay1 * ay1;
    const float B0  = -2.f * A0  * px0, B1  = -2.f * A1  * px1;
    const float By0 = -2.f * Ay0 * py0, By1 = -2.f * Ay1 * py1;
    const float C0  = A0 * px0 * px0 + Ay0 * py0 * py0;
    const float C1  = A1 * px1 * px1 + Ay1 * py1 * py1;

    const float4* __restrict__ cp   = (const float4*)(xy + start);  // 2 pts / float4
    const int*    __restrict__ segp = seg + start;
    float*        __restrict__ outP = out + q0;

    // Two accumulators per q break the serial FADD-acc chain.
    float a0a = 0.f, a0b = 0.f, a1a = 0.f, a1b = 0.f;
    int cur = segp[0];

    #define FLUSH() do {                                                   \
        atomicAdd(&outP[cur * QF],     a0a + a0b);                         \
        atomicAdd(&outP[cur * QF + 1], a1a + a1b);                         \
        a0a = 0.f; a0b = 0.f; a1a = 0.f; a1b = 0.f;                        \
    } while (0)

    #define POINT_A(X, Y) do {                                             \
        a0a += gq((X), (Y), A0, B0, C0, Ay0, By0);                         \
        a1a += gq((X), (Y), A1, B1, C1, Ay1, By1);                         \
    } while (0)
    #define POINT_B(X, Y) do {                                             \
        a0b += gq((X), (Y), A0, B0, C0, Ay0, By0);                         \
        a1b += gq((X), (Y), A1, B1, C1, Ay1, By1);                         \
    } while (0)

    // Process one 8-point stage. Hot path: sorted invariant means
    // SL8 == cur  <=>  all 8 points belong to segment 'cur'.
    #define STAGE(V0, V1, V2, V3, SL8, SPTR) do {                          \
        if ((SL8) == cur) {                                                \
            POINT_A(V0.x, V0.y);  POINT_B(V0.z, V0.w);                     \
            POINT_A(V1.x, V1.y);  POINT_B(V1.z, V1.w);                     \
            POINT_A(V2.x, V2.y);  POINT_B(V2.z, V2.w);                     \
            POINT_A(V3.x, V3.y);  POINT_B(V3.z, V3.w);                     \
        } else {                                                           \
            int sv_;                                                       \
            sv_ = (SPTR)[0]; if (sv_ != cur) { FLUSH(); cur = sv_; }       \
            POINT_A(V0.x, V0.y);                                           \
            sv_ = (SPTR)[1]; if (sv_ != cur) { FLUSH(); cur = sv_; }       \
            POINT_B(V0.z, V0.w);                                           \
            sv_ = (SPTR)[2]; if (sv_ != cur) { FLUSH(); cur = sv_; }       \
            POINT_A(V1.x, V1.y);                                           \
            sv_ = (SPTR)[3]; if (sv_ != cur) { FLUSH(); cur = sv_; }       \
            POINT_B(V1.z, V1.w);                                           \
            sv_ = (SPTR)[4]; if (sv_ != cur) { FLUSH(); cur = sv_; }       \
            POINT_A(V2.x, V2.y);                                           \
            sv_ = (SPTR)[5]; if (sv_ != cur) { FLUSH(); cur = sv_; }       \
            POINT_B(V2.z, V2.w);                                           \
            sv_ = (SPTR)[6]; if (sv_ != cur) { FLUSH(); cur = sv_; }       \
            POINT_A(V3.x, V3.y);                                           \
            sv_ = (SPTR)[7]; if (sv_ != cur) { FLUSH(); cur = sv_; }       \
            POINT_B(V3.z, V3.w);                                           \
        }                                                                  \
    } while (0)

    // Software pipeline: 8-pt stages, double-buffered, unrolled x2
    // (16 pts/iteration). Every stage's loads are issued one full stage
    // (~96 independent math instrs) before first use.
    const int nIter = (end - start) >> 4;
    float4 sA0, sA1, sA2, sA3;
    int aL = 0;
    if (nIter > 0) {
        sA0 = cp[0]; sA1 = cp[1]; sA2 = cp[2]; sA3 = cp[3];
        aL  = segp[7];
    }
    for (int it = 0; it < nIter; ++it) {
        // prefetch stage B (points 8..15 of this iteration)
        const float4 sB0 = cp[4], sB1 = cp[5], sB2 = cp[6], sB3 = cp[7];
        const int    bL  = segp[15];
        STAGE(sA0, sA1, sA2, sA3, aL, segp);
        // prefetch next iteration's stage A (points 16..23), guarded
        if (it + 1 < nIter) {
            sA0 = cp[8]; sA1 = cp[9]; sA2 = cp[10]; sA3 = cp[11];
            aL  = segp[23];
        }
        STAGE(sB0, sB1, sB2, sB3, bL, segp + 8);
        cp   += 8;
        segp += 16;
    }
    // scalar tail (< 16 points; only the last warp)
    for (int p = start + (nIter << 4); p < end; ++p, ++segp) {
        const float2 c  = xy[p];
        const int    sv = segp[0];
        if (sv != cur) { FLUSH(); cur = sv; }
        POINT_A(c.x, c.y);
    }
    FLUSH();

    #undef STAGE
    #undef FLUSH
    #undef POINT_A
    #undef POINT_B
}

extern "C" void kernel_launch(void* const* d_in, const int* in_sizes, int n_in,
                              void* d_out, int out_size) {
    const float2* xy  = (const float2*)d_in[0];
    const int*    seg = (const int*)   d_in[1];
    const float*  sp  = (const float*) d_in[2];
    const float*  isg = (const float*) d_in[3];
    float*        out = (float*)d_out;

    const int n = in_sizes[0] / 2;   // input is [N,2] float32

    const int n4 = out_size >> 2;    // 4096*64 / 4
    perslay_zero_kernel<<<(n4 + 255) / 256, 256>>>((float4*)out, n4);

    const int num_warps = (n + PTS_PER_WARP - 1) / PTS_PER_WARP;
    const int blocks    = (num_warps + 7) / 8;   // 8 warps / block
    perslay_kernel<<<blocks, 256>>>(xy, seg, sp, isg, out, n);
}

// round 10
// speedup vs baseline: 1.0757x; 1.0757x over previous
#include <cuda_runtime.h>

#define QF 64
#define PTS_PER_WARP 576   // multiple of 24; 3473 warps -> 435 blocks <= 444 (3/SM) = ONE wave

__global__ void perslay_zero_kernel(float4* __restrict__ out, int n4) {
    int i = blockIdx.x * blockDim.x + threadIdx.x;
    if (i < n4) out[i] = make_float4(0.f, 0.f, 0.f, 0.f);
}

__device__ __forceinline__ float ex2_approx(float x) {
    float r;
    asm("ex2.approx.f32 %0, %1;" : "=f"(r) : "f"(x));
    return r;
}

// phi(x,y) for one q via pure-FFMA quadratic chain:
//   t = ((A*x + B)*x + C) + (Ay*y + By)*y  == -(ax(x-px))^2-(ay(y-py))^2, log2 units
//   4 FFMA -> 1 MUFU -> 1 FADD(acc)
__device__ __forceinline__ float gq(float x, float y,
                                    float A, float B, float C,
                                    float Ay, float By)
{
    const float u = fmaf(x, A, B);
    const float v = fmaf(x, u, C);
    const float w = fmaf(y, Ay, By);
    const float t = fmaf(y, w, v);
    return ex2_approx(t);
}

__global__ __launch_bounds__(256, 3) void perslay_kernel(
    const float2* __restrict__ xy,
    const int*    __restrict__ seg,
    const float*  __restrict__ sp,
    const float*  __restrict__ isg,
    float*        __restrict__ out,
    int n)
{
    const int warp_id = blockIdx.x * (blockDim.x >> 5) + (threadIdx.x >> 5);
    const int lane    = threadIdx.x & 31;
    const int start   = warp_id * PTS_PER_WARP;
    if (start >= n) return;
    const int end = min(start + PTS_PER_WARP, n);

    const int q0 = 2 * lane;
    const int q1 = q0 + 1;

    // sqrt(log2 e) folded into sigma scale so a bare ex2 replaces exp.
    const float SL  = 1.2011224087864498f;
    const float px0 = sp[q0],      px1 = sp[q1];
    const float py0 = sp[QF + q0], py1 = sp[QF + q1];
    const float ax0 = isg[q0]      * SL, ax1 = isg[q1]      * SL;
    const float ay0 = isg[QF + q0] * SL, ay1 = isg[QF + q1] * SL;

    const float A0  = -ax0 * ax0,       A1  = -ax1 * ax1;
    const float Ay0 = -ay0 * ay0,       Ay1 = -ay1 * ay1;
    const float B0  = -2.f * A0  * px0, B1  = -2.f * A1  * px1;
    const float By0 = -2.f * Ay0 * py0, By1 = -2.f * Ay1 * py1;
    const float C0  = A0 * px0 * px0 + Ay0 * py0 * py0;
    const float C1  = A1 * px1 * px1 + Ay1 * py1 * py1;

    const float4* __restrict__ cp   = (const float4*)(xy + start);  // 2 pts / float4
    const int*    __restrict__ segp = seg + start;
    float*        __restrict__ outP = out + q0;

    // Two accumulators per q break the serial FADD-acc chain.
    float a0a = 0.f, a0b = 0.f, a1a = 0.f, a1b = 0.f;
    int cur = segp[0];

    #define FLUSH() do {                                                   \
        atomicAdd(&outP[cur * QF],     a0a + a0b);                         \
        atomicAdd(&outP[cur * QF + 1], a1a + a1b);                         \
        a0a = 0.f; a0b = 0.f; a1a = 0.f; a1b = 0.f;                        \
    } while (0)

    #define POINT_A(X, Y) do {                                             \
        a0a += gq((X), (Y), A0, B0, C0, Ay0, By0);                         \
        a1a += gq((X), (Y), A1, B1, C1, Ay1, By1);                         \
    } while (0)
    #define POINT_B(X, Y) do {                                             \
        a0b += gq((X), (Y), A0, B0, C0, Ay0, By0);                         \
        a1b += gq((X), (Y), A1, B1, C1, Ay1, By1);                         \
    } while (0)

    // Cold-arm helper: per-point segment tracking for one float4 (2 points).
    #define COLD2(V, SPTR, I) do {                                         \
        int sv_;                                                           \
        sv_ = (SPTR)[(I)];     if (sv_ != cur) { FLUSH(); cur = sv_; }     \
        POINT_A(V.x, V.y);                                                 \
        sv_ = (SPTR)[(I) + 1]; if (sv_ != cur) { FLUSH(); cur = sv_; }     \
        POINT_B(V.z, V.w);                                                 \
    } while (0)

    int p = start;
    // 24-point chunks: front-batch 12 coord LDG.128 + 1 scalar seg LDG
    // (MLP=13) so a single scoreboard wait is amortized over ~288 math
    // instructions. Sorted invariant: seg[i] >= cur for i >= p, so
    // seg[p+23]==cur <=> the whole 24-chunk belongs to 'cur'.
    for (; p + 24 <= end; p += 24, cp += 12, segp += 24) {
        const float4 cA = cp[0],  cB = cp[1],  cC = cp[2],  cD = cp[3];
        const float4 cE = cp[4],  cF = cp[5],  cG = cp[6],  cH = cp[7];
        const float4 cI = cp[8],  cJ = cp[9],  cK = cp[10], cL = cp[11];
        const int slast = segp[23];
        if (slast == cur) {
            POINT_A(cA.x, cA.y);  POINT_B(cA.z, cA.w);
            POINT_A(cB.x, cB.y);  POINT_B(cB.z, cB.w);
            POINT_A(cC.x, cC.y);  POINT_B(cC.z, cC.w);
            POINT_A(cD.x, cD.y);  POINT_B(cD.z, cD.w);
            POINT_A(cE.x, cE.y);  POINT_B(cE.z, cE.w);
            POINT_A(cF.x, cF.y);  POINT_B(cF.z, cF.w);
            POINT_A(cG.x, cG.y);  POINT_B(cG.z, cG.w);
            POINT_A(cH.x, cH.y);  POINT_B(cH.z, cH.w);
            POINT_A(cI.x, cI.y);  POINT_B(cI.z, cI.w);
            POINT_A(cJ.x, cJ.y);  POINT_B(cJ.z, cJ.w);
            POINT_A(cK.x, cK.y);  POINT_B(cK.z, cK.w);
            POINT_A(cL.x, cL.y);  POINT_B(cL.z, cL.w);
        } else {
            // Cold arm (~5% of chunks): per-point segment tracking.
            COLD2(cA, segp, 0);   COLD2(cB, segp, 2);
            COLD2(cC, segp, 4);   COLD2(cD, segp, 6);
            COLD2(cE, segp, 8);   COLD2(cF, segp, 10);
            COLD2(cG, segp, 12);  COLD2(cH, segp, 14);
            COLD2(cI, segp, 16);  COLD2(cJ, segp, 18);
            COLD2(cK, segp, 20);  COLD2(cL, segp, 22);
        }
    }
    for (; p < end; ++p, ++segp) {   // tail (< 24 points)
        const float2 c  = xy[p];
        const int    sv = segp[0];
        if (sv != cur) { FLUSH(); cur = sv; }
        POINT_A(c.x, c.y);
    }
    FLUSH();

    #undef COLD2
    #undef FLUSH
    #undef POINT_A
    #undef POINT_B
}

extern "C" void kernel_launch(void* const* d_in, const int* in_sizes, int n_in,
                              void* d_out, int out_size) {
    const float2* xy  = (const float2*)d_in[0];
    const int*    seg = (const int*)   d_in[1];
    const float*  sp  = (const float*) d_in[2];
    const float*  isg = (const float*) d_in[3];
    float*        out = (float*)d_out;

    const int n = in_sizes[0] / 2;   // input is [N,2] float32

    const int n4 = out_size >> 2;    // 4096*64 / 4
    perslay_zero_kernel<<<(n4 + 255) / 256, 256>>>((float4*)out, n4);

    const int num_warps = (n + PTS_PER_WARP - 1) / PTS_PER_WARP;
    const int blocks    = (num_warps + 7) / 8;   // 8 warps / block
    perslay_kernel<<<blocks, 256>>>(xy, seg, sp, isg, out, n);
}

// round 11
// speedup vs baseline: 1.3296x; 1.2361x over previous
#include <cuda_runtime.h>
#include <cuda_fp16.h>

#define QF 64
#define PTS_PER_WARP 432   // multiple of 16; 4630 warps -> 579 blocks <= 592 (4/SM) = ONE wave

__global__ void perslay_zero_kernel(float4* __restrict__ out, int n4) {
    int i = blockIdx.x * blockDim.x + threadIdx.x;
    if (i < n4) out[i] = make_float4(0.f, 0.f, 0.f, 0.f);
}

__device__ __forceinline__ float ex2f(float x) {
    float r;
    asm("ex2.approx.f32 %0, %1;" : "=f"(r) : "f"(x));
    return r;
}

// ex2 on both halves in ONE MUFU op.
__device__ __forceinline__ __half2 h2ex2(__half2 v) {
    unsigned a = *reinterpret_cast<unsigned*>(&v);
    unsigned r;
    asm("ex2.approx.f16x2 %0, %1;" : "=r"(r) : "r"(a));
    return *reinterpret_cast<__half2*>(&r);
}

__global__ __launch_bounds__(256, 4) void perslay_kernel(
    const float2* __restrict__ xy,
    const int*    __restrict__ seg,
    const float*  __restrict__ sp,
    const float*  __restrict__ isg,
    float*        __restrict__ out,
    int n)
{
    const int warp_id = blockIdx.x * (blockDim.x >> 5) + (threadIdx.x >> 5);
    const int lane    = threadIdx.x & 31;
    const int start   = warp_id * PTS_PER_WARP;
    if (start >= n) return;
    const int end = min(start + PTS_PER_WARP, n);

    const int q0 = 2 * lane;
    const int q1 = q0 + 1;

    // sqrt(log2 e) folded into sigma scale so a bare ex2 replaces exp.
    const float SL  = 1.2011224087864498f;
    const float px0 = sp[q0],      px1 = sp[q1];
    const float py0 = sp[QF + q0], py1 = sp[QF + q1];
    const float ax0 = isg[q0]      * SL, ax1 = isg[q1]      * SL;
    const float ay0 = isg[QF + q0] * SL, ay1 = isg[QF + q1] * SL;

    // t = A x^2 + B x + Ay y^2 + By y + C  (log2 units, all terms <= 0 shifted)
    // fp16 path computes t' = t - C; the 2^C factor is applied at flush in fp32.
    const float A0  = -ax0 * ax0,       A1  = -ax1 * ax1;
    const float Ay0 = -ay0 * ay0,       Ay1 = -ay1 * ay1;
    const float B0  = -2.f * A0  * px0, B1  = -2.f * A1  * px1;
    const float By0 = -2.f * Ay0 * py0, By1 = -2.f * Ay1 * py1;
    const float C0  = A0 * px0 * px0 + Ay0 * py0 * py0;
    const float C1  = A1 * px1 * px1 + Ay1 * py1 * py1;
    const float E0  = ex2f(C0);   // 2^C, fp32-exact scale applied at flush
    const float E1  = ex2f(C1);

    const __half2 A2  = __floats2half2_rn(A0,  A1);   // lo->q0, hi->q1
    const __half2 B2  = __floats2half2_rn(B0,  B1);
    const __half2 Ay2 = __floats2half2_rn(Ay0, Ay1);
    const __half2 By2 = __floats2half2_rn(By0, By1);
    const __half2 H2Z = __floats2half2_rn(0.f, 0.f);

    const float4* __restrict__ cp   = (const float4*)(xy + start);  // 2 pts / float4
    const int*    __restrict__ segp = seg + start;
    float*        __restrict__ outP = out + q0;

    // half2 per-chunk accumulators (<=8 adds each before drain -> bounded err),
    // fp32 per-segment accumulators.
    __half2 haA = H2Z, haB = H2Z;
    float acc0 = 0.f, acc1 = 0.f;
    int cur = segp[0];

    // Per point, both q's at once:
    //   u = A*x+B; w = Ay*y+By; t' = x*u + y*w; acc += 2^t'
    //   2 cvt + 3 HFMA2/HMUL2 + 1 HFMA2 + 1 MUFU(f16x2) + 1 HADD2 = 8 ops.
    #define POINT_A(X, Y) do {                                             \
        const __half2 xx_ = __float2half2_rn(X);                           \
        const __half2 yy_ = __float2half2_rn(Y);                           \
        const __half2 u_  = __hfma2(xx_, A2, B2);                          \
        const __half2 w_  = __hfma2(yy_, Ay2, By2);                        \
        const __half2 t_  = __hfma2(yy_, w_, __hmul2(xx_, u_));            \
        haA = __hadd2(haA, h2ex2(t_));                                     \
    } while (0)
    #define POINT_B(X, Y) do {                                             \
        const __half2 xx_ = __float2half2_rn(X);                           \
        const __half2 yy_ = __float2half2_rn(Y);                           \
        const __half2 u_  = __hfma2(xx_, A2, B2);                          \
        const __half2 w_  = __hfma2(yy_, Ay2, By2);                        \
        const __half2 t_  = __hfma2(yy_, w_, __hmul2(xx_, u_));            \
        haB = __hadd2(haB, h2ex2(t_));                                     \
    } while (0)

    // Drain half2 accumulators into fp32 (per chunk + before any flush).
    #define DRAIN() do {                                                   \
        const float2 fa_ = __half22float2(__hadd2(haA, haB));              \
        acc0 += fa_.x; acc1 += fa_.y;                                      \
        haA = H2Z; haB = H2Z;                                              \
    } while (0)

    #define FLUSH() do {                                                   \
        DRAIN();                                                           \
        atomicAdd(&outP[cur * QF],     acc0 * E0);                         \
        atomicAdd(&outP[cur * QF + 1], acc1 * E1);                         \
        acc0 = 0.f; acc1 = 0.f;                                            \
    } while (0)

    int p = start;
    // 16-point chunks: front-batch 8 coord LDG.128 + 1 scalar seg LDG (MLP=9).
    // Sorted invariant: seg[i] >= cur for i >= p, so seg[p+15]==cur <=> the
    // whole chunk belongs to 'cur'.
    for (; p + 16 <= end; p += 16, cp += 8, segp += 16) {
        const float4 cA = cp[0], cB = cp[1], cC = cp[2], cD = cp[3];
        const float4 cE = cp[4], cF = cp[5], cG = cp[6], cH = cp[7];
        const int slast = segp[15];
        if (slast == cur) {
            POINT_A(cA.x, cA.y);  POINT_B(cA.z, cA.w);
            POINT_A(cB.x, cB.y);  POINT_B(cB.z, cB.w);
            POINT_A(cC.x, cC.y);  POINT_B(cC.z, cC.w);
            POINT_A(cD.x, cD.y);  POINT_B(cD.z, cD.w);
            POINT_A(cE.x, cE.y);  POINT_B(cE.z, cE.w);
            POINT_A(cF.x, cF.y);  POINT_B(cF.z, cF.w);
            POINT_A(cG.x, cG.y);  POINT_B(cG.z, cG.w);
            POINT_A(cH.x, cH.y);  POINT_B(cH.z, cH.w);
        } else {
            // Cold arm (~3% of chunks): per-point segment tracking.
            int sv;
            sv = segp[0];  if (sv != cur) { FLUSH(); cur = sv; }
            POINT_A(cA.x, cA.y);
            sv = segp[1];  if (sv != cur) { FLUSH(); cur = sv; }
            POINT_B(cA.z, cA.w);
            sv = segp[2];  if (sv != cur) { FLUSH(); cur = sv; }
            POINT_A(cB.x, cB.y);
            sv = segp[3];  if (sv != cur) { FLUSH(); cur = sv; }
            POINT_B(cB.z, cB.w);
            sv = segp[4];  if (sv != cur) { FLUSH(); cur = sv; }
            POINT_A(cC.x, cC.y);
            sv = segp[5];  if (sv != cur) { FLUSH(); cur = sv; }
            POINT_B(cC.z, cC.w);
            sv = segp[6];  if (sv != cur) { FLUSH(); cur = sv; }
            POINT_A(cD.x, cD.y);
            sv = segp[7];  if (sv != cur) { FLUSH(); cur = sv; }
            POINT_B(cD.z, cD.w);
            sv = segp[8];  if (sv != cur) { FLUSH(); cur = sv; }
            POINT_A(cE.x, cE.y);
            sv = segp[9];  if (sv != cur) { FLUSH(); cur = sv; }
            POINT_B(cE.z, cE.w);
            sv = segp[10]; if (sv != cur) { FLUSH(); cur = sv; }
            POINT_A(cF.x, cF.y);
            sv = segp[11]; if (sv != cur) { FLUSH(); cur = sv; }
            POINT_B(cF.z, cF.w);
            sv = segp[12]; if (sv != cur) { FLUSH(); cur = sv; }
            POINT_A(cG.x, cG.y);
            sv = segp[13]; if (sv != cur) { FLUSH(); cur = sv; }
            POINT_B(cG.z, cG.w);
            sv = segp[14]; if (sv != cur) { FLUSH(); cur = sv; }
            POINT_A(cH.x, cH.y);
            sv = segp[15]; if (sv != cur) { FLUSH(); cur = sv; }
            POINT_B(cH.z, cH.w);
        }
        DRAIN();   // bound fp16 accumulation length to one chunk
    }
    for (; p < end; ++p, ++segp) {   // tail (< 16 points)
        const float2 c  = xy[p];
        const int    sv = segp[0];
        if (sv != cur) { FLUSH(); cur = sv; }
        POINT_A(c.x, c.y);
    }
    FLUSH();

    #undef FLUSH
    #undef DRAIN
    #undef POINT_A
    #undef POINT_B
}

extern "C" void kernel_launch(void* const* d_in, const int* in_sizes, int n_in,
                              void* d_out, int out_size) {
    const float2* xy  = (const float2*)d_in[0];
    const int*    seg = (const int*)   d_in[1];
    const float*  sp  = (const float*) d_in[2];
    const float*  isg = (const float*) d_in[3];
    float*        out = (float*)d_out;

    const int n = in_sizes[0] / 2;   // input is [N,2] float32

    const int n4 = out_size >> 2;    // 4096*64 / 4
    perslay_zero_kernel<<<(n4 + 255) / 256, 256>>>((float4*)out, n4);

    const int num_warps = (n + PTS_PER_WARP - 1) / PTS_PER_WARP;
    const int blocks    = (num_warps + 7) / 8;   // 8 warps / block
    perslay_kernel<<<blocks, 256>>>(xy, seg, sp, isg, out, n);
}

// round 12
// speedup vs baseline: 1.3316x; 1.0015x over previous
#include <cuda_runtime.h>
#include <cuda_fp16.h>

#define QF 64
#define PTS_PER_WARP 576   // multiple of 24; 3473 warps -> 435 blocks <= 444 (3/SM) = ONE wave

__global__ void perslay_zero_kernel(float4* __restrict__ out, int n4) {
    int i = blockIdx.x * blockDim.x + threadIdx.x;
    if (i < n4) out[i] = make_float4(0.f, 0.f, 0.f, 0.f);
}

__device__ __forceinline__ float ex2f(float x) {
    float r;
    asm("ex2.approx.f32 %0, %1;" : "=f"(r) : "f"(x));
    return r;
}

// ex2 on both halves in ONE MUFU op.
__device__ __forceinline__ __half2 h2ex2(__half2 v) {
    unsigned a = *reinterpret_cast<unsigned*>(&v);
    unsigned r;
    asm("ex2.approx.f16x2 %0, %1;" : "=r"(r) : "r"(a));
    return *reinterpret_cast<__half2*>(&r);
}

__global__ __launch_bounds__(256, 3) void perslay_kernel(
    const float2* __restrict__ xy,
    const int*    __restrict__ seg,
    const float*  __restrict__ sp,
    const float*  __restrict__ isg,
    float*        __restrict__ out,
    int n)
{
    const int warp_id = blockIdx.x * (blockDim.x >> 5) + (threadIdx.x >> 5);
    const int lane    = threadIdx.x & 31;
    const int start   = warp_id * PTS_PER_WARP;
    if (start >= n) return;
    const int end = min(start + PTS_PER_WARP, n);

    const int q0 = 2 * lane;
    const int q1 = q0 + 1;

    // sqrt(log2 e) folded into sigma scale so a bare ex2 replaces exp.
    const float SL  = 1.2011224087864498f;
    const float px0 = sp[q0],      px1 = sp[q1];
    const float py0 = sp[QF + q0], py1 = sp[QF + q1];
    const float ax0 = isg[q0]      * SL, ax1 = isg[q1]      * SL;
    const float ay0 = isg[QF + q0] * SL, ay1 = isg[QF + q1] * SL;

    // t = A x^2 + B x + Ay y^2 + By y + C  (log2 units). fp16 path computes
    // t' = t - C; the 2^C factor is applied at flush in fp32.
    const float A0  = -ax0 * ax0,       A1  = -ax1 * ax1;
    const float Ay0 = -ay0 * ay0,       Ay1 = -ay1 * ay1;
    const float B0  = -2.f * A0  * px0, B1  = -2.f * A1  * px1;
    const float By0 = -2.f * Ay0 * py0, By1 = -2.f * Ay1 * py1;
    const float C0  = A0 * px0 * px0 + Ay0 * py0 * py0;
    const float C1  = A1 * px1 * px1 + Ay1 * py1 * py1;
    const float E0  = ex2f(C0);   // 2^C, fp32-exact scale applied at flush
    const float E1  = ex2f(C1);

    const __half2 A2  = __floats2half2_rn(A0,  A1);   // lo->q0, hi->q1
    const __half2 B2  = __floats2half2_rn(B0,  B1);
    const __half2 Ay2 = __floats2half2_rn(Ay0, Ay1);
    const __half2 By2 = __floats2half2_rn(By0, By1);
    const __half2 H2Z = __floats2half2_rn(0.f, 0.f);

    const float4* __restrict__ cp   = (const float4*)(xy + start);  // 2 pts / float4
    const int*    __restrict__ segp = seg + start;
    float*        __restrict__ outP = out + q0;

    // Three rotating half2 accumulators: <=8 adds each per 24-pt chunk
    // (same bound as the validated 16-pt/2-acc config) + fp32 carries.
    __half2 haA = H2Z, haB = H2Z, haC = H2Z;
    float acc0 = 0.f, acc1 = 0.f;
    int cur = segp[0];

    // Per point, both q's at once:
    //   u = A*x+B; w = Ay*y+By; t' = x*u + y*w; acc += 2^t'
    #define PBODY(X, Y, HACC) do {                                         \
        const __half2 xx_ = __float2half2_rn(X);                           \
        const __half2 yy_ = __float2half2_rn(Y);                           \
        const __half2 u_  = __hfma2(xx_, A2, B2);                          \
        const __half2 w_  = __hfma2(yy_, Ay2, By2);                        \
        const __half2 t_  = __hfma2(yy_, w_, __hmul2(xx_, u_));            \
        HACC = __hadd2(HACC, h2ex2(t_));                                   \
    } while (0)
    #define POINT_A(X, Y) PBODY(X, Y, haA)
    #define POINT_B(X, Y) PBODY(X, Y, haB)
    #define POINT_C(X, Y) PBODY(X, Y, haC)

    // Drain half2 accumulators into fp32 (per chunk + before any flush).
    #define DRAIN() do {                                                   \
        const float2 fa_ = __half22float2(__hadd2(__hadd2(haA, haB), haC));\
        acc0 += fa_.x; acc1 += fa_.y;                                      \
        haA = H2Z; haB = H2Z; haC = H2Z;                                   \
    } while (0)

    #define FLUSH() do {                                                   \
        DRAIN();                                                           \
        atomicAdd(&outP[cur * QF],     acc0 * E0);                         \
        atomicAdd(&outP[cur * QF + 1], acc1 * E1);                         \
        acc0 = 0.f; acc1 = 0.f;                                            \
    } while (0)

    // Cold-arm helper: per-point segment tracking for one float4 (2 points).
    #define COLD2(V, SPTR, I, PM0, PM1) do {                               \
        int sv_;                                                           \
        sv_ = (SPTR)[(I)];     if (sv_ != cur) { FLUSH(); cur = sv_; }     \
        PM0(V.x, V.y);                                                     \
        sv_ = (SPTR)[(I) + 1]; if (sv_ != cur) { FLUSH(); cur = sv_; }     \
        PM1(V.z, V.w);                                                     \
    } while (0)

    int p = start;
    // 24-point chunks: front-batch 12 coord LDG.128 + 1 scalar seg LDG
    // (MLP=13); ~190 independent math instrs amortize one scoreboard wait.
    // Sorted invariant: seg[i] >= cur for i >= p, so seg[p+23]==cur <=> the
    // whole chunk belongs to 'cur'.
    for (; p + 24 <= end; p += 24, cp += 12, segp += 24) {
        const float4 cA = cp[0],  cB = cp[1],  cC = cp[2],  cD = cp[3];
        const float4 cE = cp[4],  cF = cp[5],  cG = cp[6],  cH = cp[7];
        const float4 cI = cp[8],  cJ = cp[9],  cK = cp[10], cL = cp[11];
        const int slast = segp[23];
        if (slast == cur) {
            POINT_A(cA.x, cA.y);  POINT_B(cA.z, cA.w);
            POINT_C(cB.x, cB.y);  POINT_A(cB.z, cB.w);
            POINT_B(cC.x, cC.y);  POINT_C(cC.z, cC.w);
            POINT_A(cD.x, cD.y);  POINT_B(cD.z, cD.w);
            POINT_C(cE.x, cE.y);  POINT_A(cE.z, cE.w);
            POINT_B(cF.x, cF.y);  POINT_C(cF.z, cF.w);
            POINT_A(cG.x, cG.y);  POINT_B(cG.z, cG.w);
            POINT_C(cH.x, cH.y);  POINT_A(cH.z, cH.w);
            POINT_B(cI.x, cI.y);  POINT_C(cI.z, cI.w);
            POINT_A(cJ.x, cJ.y);  POINT_B(cJ.z, cJ.w);
            POINT_C(cK.x, cK.y);  POINT_A(cK.z, cK.w);
            POINT_B(cL.x, cL.y);  POINT_C(cL.z, cL.w);
        } else {
            // Cold arm (~5% of chunks): per-point segment tracking.
            COLD2(cA, segp, 0,  POINT_A, POINT_B);
            COLD2(cB, segp, 2,  POINT_C, POINT_A);
            COLD2(cC, segp, 4,  POINT_B, POINT_C);
            COLD2(cD, segp, 6,  POINT_A, POINT_B);
            COLD2(cE, segp, 8,  POINT_C, POINT_A);
            COLD2(cF, segp, 10, POINT_B, POINT_C);
            COLD2(cG, segp, 12, POINT_A, POINT_B);
            COLD2(cH, segp, 14, POINT_C, POINT_A);
            COLD2(cI, segp, 16, POINT_B, POINT_C);
            COLD2(cJ, segp, 18, POINT_A, POINT_B);
            COLD2(cK, segp, 20, POINT_C, POINT_A);
            COLD2(cL, segp, 22, POINT_B, POINT_C);
        }
        DRAIN();   // bound fp16 accumulation length to one chunk
    }
    for (; p < end; ++p, ++segp) {   // tail (< 24 points)
        const float2 c  = xy[p];
        const int    sv = segp[0];
        if (sv != cur) { FLUSH(); cur = sv; }
        POINT_A(c.x, c.y);
    }
    FLUSH();

    #undef COLD2
    #undef FLUSH
    #undef DRAIN
    #undef POINT_A
    #undef POINT_B
    #undef POINT_C
    #undef PBODY
}

extern "C" void kernel_launch(void* const* d_in, const int* in_sizes, int n_in,
                              void* d_out, int out_size) {
    const float2* xy  = (const float2*)d_in[0];
    const int*    seg = (const int*)   d_in[1];
    const float*  sp  = (const float*) d_in[2];
    const float*  isg = (const float*) d_in[3];
    float*        out = (float*)d_out;

    const int n = in_sizes[0] / 2;   // input is [N,2] float32

    const int n4 = out_size >> 2;    // 4096*64 / 4
    perslay_zero_kernel<<<(n4 + 255) / 256, 256>>>((float4*)out, n4);

    const int num_warps = (n + PTS_PER_WARP - 1) / PTS_PER_WARP;
    const int blocks    = (num_warps + 7) / 8;   // 8 warps / block
    perslay_kernel<<<blocks, 256>>>(xy, seg, sp, isg, out, n);
}